// round 1
// baseline (speedup 1.0000x reference)
#include <cuda_runtime.h>

// DCTExtractor: gray = 0.299R + 0.587G + 0.114B over (64,3,512,512);
// per 8x8 block: D @ G @ D^T, elementwise * mask; output (64,1,512,512).
//
// One thread per 8x8 tile. Purely HBM-bound: 201MB read + 67MB write.

#define H 512
#define W 512
#define CHAN (H * W)        // 262144 elements per channel
#define TILES_PER_IMG (64 * 64)
#define N_TILES (64 * TILES_PER_IMG)   // 262144
#define THREADS 256

__global__ __launch_bounds__(THREADS)
void dct_extract_kernel(const float* __restrict__ x,
                        const float* __restrict__ dctm,
                        const float* __restrict__ mask,
                        float* __restrict__ out)
{
    __shared__ float sD[64];
    __shared__ float sM[64];
    const int tid = threadIdx.x;
    if (tid < 64) {
        sD[tid] = dctm[tid];
        sM[tid] = mask[tid];
    }
    __syncthreads();

    const int id = blockIdx.x * THREADS + tid;   // 0 .. N_TILES-1 exactly
    const int tw = id & 63;          // tile col
    const int th = (id >> 6) & 63;   // tile row
    const int b  = id >> 12;         // batch

    const size_t img_off = (size_t)b * 3 * CHAN + (size_t)(th * 8) * W + (size_t)(tw * 8);
    const float* base = x + img_off;

    // Load 8x8 window of R,G,B; fuse into grayscale registers.
    float g[8][8];
#pragma unroll
    for (int r = 0; r < 8; r++) {
        const float* p = base + (size_t)r * W;
        float4 r0 = *(const float4*)(p);
        float4 r1 = *(const float4*)(p + 4);
        float4 gg0 = *(const float4*)(p + CHAN);
        float4 gg1 = *(const float4*)(p + CHAN + 4);
        float4 b0 = *(const float4*)(p + 2 * CHAN);
        float4 b1 = *(const float4*)(p + 2 * CHAN + 4);
        g[r][0] = 0.299f * r0.x + 0.587f * gg0.x + 0.114f * b0.x;
        g[r][1] = 0.299f * r0.y + 0.587f * gg0.y + 0.114f * b0.y;
        g[r][2] = 0.299f * r0.z + 0.587f * gg0.z + 0.114f * b0.z;
        g[r][3] = 0.299f * r0.w + 0.587f * gg0.w + 0.114f * b0.w;
        g[r][4] = 0.299f * r1.x + 0.587f * gg1.x + 0.114f * b1.x;
        g[r][5] = 0.299f * r1.y + 0.587f * gg1.y + 0.114f * b1.y;
        g[r][6] = 0.299f * r1.z + 0.587f * gg1.z + 0.114f * b1.z;
        g[r][7] = 0.299f * r1.w + 0.587f * gg1.w + 0.114f * b1.w;
    }

    // out = (D @ G @ D^T) * mask, one output row at a time to cap registers.
    float* o = out + (size_t)b * CHAN + (size_t)(th * 8) * W + (size_t)(tw * 8);
#pragma unroll
    for (int i = 0; i < 8; i++) {
        float t[8];
#pragma unroll
        for (int k = 0; k < 8; k++) {
            float acc = 0.0f;
#pragma unroll
            for (int j = 0; j < 8; j++)
                acc = fmaf(sD[i * 8 + j], g[j][k], acc);
            t[k] = acc;
        }
        float rr[8];
#pragma unroll
        for (int l = 0; l < 8; l++) {
            float acc = 0.0f;
#pragma unroll
            for (int k = 0; k < 8; k++)
                acc = fmaf(t[k], sD[l * 8 + k], acc);
            rr[l] = acc * sM[i * 8 + l];
        }
        float4 o0 = make_float4(rr[0], rr[1], rr[2], rr[3]);
        float4 o1 = make_float4(rr[4], rr[5], rr[6], rr[7]);
        *(float4*)(o + (size_t)i * W)     = o0;
        *(float4*)(o + (size_t)i * W + 4) = o1;
    }
}

extern "C" void kernel_launch(void* const* d_in, const int* in_sizes, int n_in,
                              void* d_out, int out_size)
{
    const float* x    = (const float*)d_in[0];
    const float* dctm = (const float*)d_in[1];
    const float* mask = (const float*)d_in[2];
    float* out = (float*)d_out;

    dct_extract_kernel<<<N_TILES / THREADS, THREADS>>>(x, dctm, mask, out);
}

// round 2
// speedup vs baseline: 1.0868x; 1.0868x over previous
#include <cuda_runtime.h>

// DCTExtractor: gray = 0.299R + 0.587G + 0.114B over (64,3,512,512);
// per 8x8 block: D @ G @ D^T, elementwise * mask; output (64,1,512,512).
//
// Two threads per 8x8 tile (column halves). Column-DCT accumulated on the fly
// (U = D @ G restricted to 4 columns, 32 regs), row-DCT partials exchanged
// between pair threads via shfl_xor(1). Purely HBM-bound: 201MB read + 67MB write.

#define H 512
#define W 512
#define CHAN (H * W)
#define N_TILES (64 * 64 * 64)        // 262144
#define N_UNITS (N_TILES * 2)         // 524288 half-tiles
#define THREADS 256

__global__ __launch_bounds__(THREADS, 3)
void dct_extract_kernel(const float* __restrict__ x,
                        const float* __restrict__ dctm,
                        const float* __restrict__ mask,
                        float* __restrict__ out)
{
    __shared__ float sD[64];
    __shared__ float sM[64];
    const int tid = threadIdx.x;
    if (tid < 64) {
        sD[tid] = dctm[tid];
        sM[tid] = mask[tid];
    }
    __syncthreads();

    const int gid = blockIdx.x * THREADS + tid;   // 0 .. N_UNITS-1
    const int h   = gid & 1;                      // column half: 0 -> cols 0-3, 1 -> cols 4-7
    const int id  = gid >> 1;                     // tile id
    const int tw  = id & 63;
    const int th  = (id >> 6) & 63;
    const int b   = id >> 12;
    const int hb  = h * 4;                        // my column base within tile

    const float* base = x + (size_t)b * 3 * CHAN
                          + (size_t)(th * 8) * W + (size_t)(tw * 8 + hb);

    // U[i][c] = sum_r D[i][r] * gray[r][c], accumulated while streaming rows.
    float U[8][4];
#pragma unroll
    for (int i = 0; i < 8; i++)
#pragma unroll
        for (int c = 0; c < 4; c++)
            U[i][c] = 0.0f;

#pragma unroll
    for (int r = 0; r < 8; r++) {
        const float* p = base + (size_t)r * W;
        float4 R = *(const float4*)(p);
        float4 G = *(const float4*)(p + CHAN);
        float4 Bv = *(const float4*)(p + 2 * CHAN);
        float gr0 = 0.299f * R.x + 0.587f * G.x + 0.114f * Bv.x;
        float gr1 = 0.299f * R.y + 0.587f * G.y + 0.114f * Bv.y;
        float gr2 = 0.299f * R.z + 0.587f * G.z + 0.114f * Bv.z;
        float gr3 = 0.299f * R.w + 0.587f * G.w + 0.114f * Bv.w;
#pragma unroll
        for (int i = 0; i < 8; i++) {
            const float d = sD[i * 8 + r];
            U[i][0] = fmaf(d, gr0, U[i][0]);
            U[i][1] = fmaf(d, gr1, U[i][1]);
            U[i][2] = fmaf(d, gr2, U[i][2]);
            U[i][3] = fmaf(d, gr3, U[i][3]);
        }
    }

    // Row DCT: out[i][l] = sum_k U_full[i][k] * D[l][k], split over the pair.
    float* o = out + (size_t)b * CHAN
                   + (size_t)(th * 8) * W + (size_t)(tw * 8 + hb);
#pragma unroll
    for (int i = 0; i < 8; i++) {
        float p8[8];
#pragma unroll
        for (int l = 0; l < 8; l++) {
            float acc = 0.0f;
#pragma unroll
            for (int kc = 0; kc < 4; kc++)
                acc = fmaf(U[i][kc], sD[l * 8 + hb + kc], acc);
            p8[l] = acc;
        }
        float res[4];
#pragma unroll
        for (int j = 0; j < 4; j++) {
            // I keep the partial for my own output column, send the partner's.
            float send = h ? p8[j] : p8[4 + j];
            float keep = h ? p8[4 + j] : p8[j];
            float w = __shfl_xor_sync(0xFFFFFFFFu, send, 1);
            res[j] = (keep + w) * sM[i * 8 + hb + j];
        }
        *(float4*)(o + (size_t)i * W) = make_float4(res[0], res[1], res[2], res[3]);
    }
}

extern "C" void kernel_launch(void* const* d_in, const int* in_sizes, int n_in,
                              void* d_out, int out_size)
{
    const float* x    = (const float*)d_in[0];
    const float* dctm = (const float*)d_in[1];
    const float* mask = (const float*)d_in[2];
    float* out = (float*)d_out;

    dct_extract_kernel<<<N_UNITS / THREADS, THREADS>>>(x, dctm, mask, out);
}